// round 10
// baseline (speedup 1.0000x reference)
#include <cuda_runtime.h>
#include <cuda_fp16.h>
#include <cstdint>

#define TM      256
#define NBLK    17
// ---- fallback (mma.sync) W layout: per-lane-contiguous, pitch 68 ----
#define SLOTP   68
#define WBLK_U  (32 * SLOTP)        // 2176 uints per block
#define WBLK_V4 (WBLK_U / 4)        // 544
// ---- tcgen05 W layout: SW128 blocked-atom f16 image, 8 KB per block ----
#define TCBLK_U  2048
#define TCBLK_V4 512

__device__ uint4 W_img[NBLK * WBLK_V4];   // fallback image
__device__ uint4 W_tc [NBLK * TCBLK_V4];  // tcgen05 image

// tcgen05 dynamic-smem layout (from a 1024-aligned base):
//   Z (A tiles)  : 2 buffers x 32768 B  (each: subtile0 16 KB | subtile1 16 KB, SW128 atoms)
//   W            : 3 buffers x 8192 B
//   bond         : 17 * 256 * 4 B
//   hdr          : tmem ptr + 2 mbarriers
#define OFF_W    65536
#define OFF_BOND 90112
#define OFF_HDR  107520
#define DSM_SZ   (107552 + 1024)

// ---------------- shared helpers ----------------
static __device__ __forceinline__ void cp_async16(uint32_t s, const void* g) {
    asm volatile("cp.async.cg.shared.global [%0], [%1], 16;" :: "r"(s), "l"(g));
}
static __device__ __forceinline__ uint32_t smem_u32(const void* p) {
    uint32_t a;
    asm("{ .reg .u64 t; cvta.to.shared.u64 t, %1; cvt.u32.u64 %0, t; }" : "=r"(a) : "l"(p));
    return a;
}
static __device__ __forceinline__ uint32_t h2u(__half2 h) {
    return *reinterpret_cast<uint32_t*>(&h);
}
static __device__ __forceinline__ __half2 u2h(uint32_t u) {
    return *reinterpret_cast<__half2*>(&u);
}
static __device__ __forceinline__ void red4(float* p, float a, float b, float c, float d) {
    asm volatile("red.global.add.v4.f32 [%0], {%1, %2, %3, %4};"
                 :: "l"(p), "f"(a), "f"(b), "f"(c), "f"(d) : "memory");
}
static __device__ __forceinline__ void mma16816(float* c, uint32_t a0, uint32_t a1,
                                                uint32_t a2, uint32_t a3,
                                                uint32_t b0, uint32_t b1) {
    asm volatile(
        "mma.sync.aligned.m16n8k16.row.col.f32.f16.f16.f32 "
        "{%0,%1,%2,%3}, {%4,%5,%6,%7}, {%8,%9}, {%0,%1,%2,%3};"
        : "+f"(c[0]), "+f"(c[1]), "+f"(c[2]), "+f"(c[3])
        : "r"(a0), "r"(a1), "r"(a2), "r"(a3), "r"(b0), "r"(b1));
}

// ---------------- tcgen05 helpers ----------------
#if defined(__CUDA_ARCH__) && defined(__CUDA_ARCH_FEAT_SM103_ALL)
#define TC_IDESC ((1u << 4) | (8u << 17) | (8u << 24))   // kind::f16: fp16 in, f32 acc, M=128, N=64
#define DBASE ((2ull << 61) | (1ull << 46) | (64ull << 32) | (1ull << 16))  // SW128, v1, SBO=64, LBO=1

static __device__ __forceinline__ bool elect1() {
    uint32_t p;
    asm volatile("{ .reg .pred P; elect.sync _|P, 0xFFFFFFFF; selp.b32 %0, 1, 0, P; }" : "=r"(p));
    return p != 0;
}
static __device__ __forceinline__ void mbar_init(uint32_t a, uint32_t c) {
    asm volatile("mbarrier.init.shared.b64 [%0], %1;" :: "r"(a), "r"(c) : "memory");
}
static __device__ __forceinline__ void mbar_wait(uint32_t a, uint32_t ph) {
    asm volatile(
        "{ .reg .pred P;\n"
        "LW_%=:\n"
        "mbarrier.try_wait.parity.acquire.cta.shared::cta.b64 P, [%0], %1, 0x989680;\n"
        "@!P bra LW_%=;\n"
        "}" :: "r"(a), "r"(ph) : "memory");
}
// SS form: BOTH operands via smem descriptors.
static __device__ __forceinline__ void tc_mma_f16_ss(uint32_t d, uint64_t ad, uint64_t bd,
                                                     uint32_t en) {
    asm volatile(
        "{ .reg .pred p; setp.ne.u32 p, %5, 0;\n"
        "tcgen05.mma.cta_group::1.kind::f16 [%0], %1, %2, %3, {%4, %4, %4, %4}, p;\n"
        "}"
        :: "r"(d), "l"(ad), "l"(bd), "r"(TC_IDESC), "r"(0u), "r"(en) : "memory");
}
static __device__ __forceinline__ void tmem_ld32(uint32_t* r, uint32_t addr) {
    asm volatile(
        "tcgen05.ld.sync.aligned.32x32b.x32.b32 "
        "{%0,%1,%2,%3,%4,%5,%6,%7,%8,%9,%10,%11,%12,%13,%14,%15,"
        "%16,%17,%18,%19,%20,%21,%22,%23,%24,%25,%26,%27,%28,%29,%30,%31}, [%32];"
        : "=r"(r[0]),  "=r"(r[1]),  "=r"(r[2]),  "=r"(r[3]),
          "=r"(r[4]),  "=r"(r[5]),  "=r"(r[6]),  "=r"(r[7]),
          "=r"(r[8]),  "=r"(r[9]),  "=r"(r[10]), "=r"(r[11]),
          "=r"(r[12]), "=r"(r[13]), "=r"(r[14]), "=r"(r[15]),
          "=r"(r[16]), "=r"(r[17]), "=r"(r[18]), "=r"(r[19]),
          "=r"(r[20]), "=r"(r[21]), "=r"(r[22]), "=r"(r[23]),
          "=r"(r[24]), "=r"(r[25]), "=r"(r[26]), "=r"(r[27]),
          "=r"(r[28]), "=r"(r[29]), "=r"(r[30]), "=r"(r[31])
        : "r"(addr));
}
#endif

// ---------------- zero output + pack both W images ----------------
__global__ void __launch_bounds__(256)
zero_pack(const float* __restrict__ K, const float* __restrict__ bias,
          float4* __restrict__ out4, int n_out4) {
    int idx = blockIdx.x * blockDim.x + threadIdx.x;
    if (idx < n_out4) out4[idx] = make_float4(0.f, 0.f, 0.f, 0.f);
    if (idx < NBLK * 2048) {
        int b = idx >> 11, r = idx & 2047;
        // fallback image: per-lane-contiguous values
        {
            int slot = r >> 6, v = r & 63;
            int gid = slot >> 2, tig = slot & 3;
            int s = v >> 4, r2 = v & 15, nt = r2 >> 1, h = r2 & 1;
            int p = 8 * s + tig + 4 * h;
            int n = nt * 8 + gid;
            float v0, v1;
            if (b < 16) { v0 = K[b * 4096 + n * 64 + 2 * p]; v1 = K[b * 4096 + n * 64 + 2 * p + 1]; }
            else        { v0 = bias[n * 64 + 2 * p];          v1 = bias[n * 64 + 2 * p + 1]; }
            ((uint32_t*)W_img)[b * WBLK_U + slot * SLOTP + v] = h2u(__floats2half2_rn(v0, v1));
        }
        // tcgen05 image: B[n][k] f16, SW128 atoms (8 rows x 128 B)
        {
            int n = r >> 5, p = r & 31;
            float v0, v1;
            if (b < 16) { v0 = K[b * 4096 + n * 64 + 2 * p]; v1 = K[b * 4096 + n * 64 + 2 * p + 1]; }
            else        { v0 = bias[n * 64 + 2 * p];          v1 = bias[n * 64 + 2 * p + 1]; }
            int byte = (n >> 3) * 1024 + (n & 7) * 128 + p * 4;
            int sw = byte ^ ((byte >> 3) & 0x70);
            ((uint32_t*)W_tc)[b * TCBLK_U + (sw >> 2)] = h2u(__floats2half2_rn(v0, v1));
        }
    }
}

extern __shared__ char dsm_raw[];

__global__ void __launch_bounds__(256, 2)
edge_main(const float* __restrict__ atom, const float* __restrict__ bondf,
          const int* __restrict__ pair, float* __restrict__ out, int n_edges)
{
    const int tid  = threadIdx.x;
    const int warp = tid >> 5;
    const int e0   = blockIdx.x * TM;

#if defined(__CUDA_ARCH__) && defined(__CUDA_ARCH_FEAT_SM103_ALL)
    // ========== tcgen05 SS-mode path: Z built in SMEM, no TMEM A-staging ==========
    const uint32_t raw  = smem_u32(dsm_raw);
    const uint32_t base = (raw + 1023u) & ~1023u;
    char* SA = dsm_raw + (base - raw);                 // 1024-aligned generic pointer

    const uint32_t ZB   = base;                        // 2 x 32768
    const uint32_t WS   = base + OFF_W;                // 3 x 8192
    uint32_t* bond_h    = (uint32_t*)(SA + OFF_BOND);  // [17][256]
    const uint32_t TP   = base + OFF_HDR;
    const uint32_t MB0  = TP + 8;
    const uint32_t MB1  = TP + 16;

    const int sub = tid >> 7;            // M-subtile
    const int row = tid & 127;           // row within subtile
    const int e   = e0 + tid;

    // Alloc THEN relinquish, both on warp 0, sequential in program order.
    if (warp == 0) {
        asm volatile("tcgen05.alloc.cta_group::1.sync.aligned.shared::cta.b32 [%0], %1;"
                     :: "r"(TP), "r"(128u) : "memory");
        asm volatile("tcgen05.relinquish_alloc_permit.cta_group::1.sync.aligned;");
    }
    if (tid == 0) { mbar_init(MB0, 1); mbar_init(MB1, 1); }

    // Stage W_0, W_1 (groups 0, 1).
    #pragma unroll
    for (int g = 0; g < 2; g++) {
        for (int i = tid; i < TCBLK_V4; i += 256)
            cp_async16(WS + g * 8192 + i * 16, W_tc + g * TCBLK_V4 + i);
        asm volatile("cp.async.commit_group;");
    }

    // Stage bond (dup half2); src in register; gather neighbor row -> 32 half2 regs.
    int src = -1, nbr = 0;
    {
        float4 q0 = {0,0,0,0}, q1 = q0, q2 = q0, q3 = q0;
        float one = 0.f;
        if (e < n_edges) {
            int2 pr = ((const int2*)pair)[e];
            src = pr.x; nbr = pr.y; one = 1.f;
            const float4* bp = (const float4*)(bondf + (size_t)e * 16);
            q0 = bp[0]; q1 = bp[1]; q2 = bp[2]; q3 = bp[3];
        }
        const float bv[16] = {q0.x,q0.y,q0.z,q0.w, q1.x,q1.y,q1.z,q1.w,
                              q2.x,q2.y,q2.z,q2.w, q3.x,q3.y,q3.z,q3.w};
        #pragma unroll
        for (int b = 0; b < 16; b++) bond_h[b * TM + tid] = h2u(__float2half2_rn(bv[b]));
        bond_h[16 * TM + tid] = h2u(__float2half2_rn(one));
    }
    __half2 nb[32];
    {
        const float4* ap = (const float4*)(atom + (size_t)nbr * 64);
        #pragma unroll
        for (int q = 0; q < 16; q++) {
            float4 v = __ldg(ap + q);
            nb[2 * q]     = __floats2half2_rn(v.x, v.y);
            nb[2 * q + 1] = __floats2half2_rn(v.z, v.w);
        }
    }

    // This thread's Z row base (within a Z buffer) + swizzle phase.
    // Z buffer: subtile s at +s*16384; row r: atom (r>>3)*1024 + (r&7)*128; SW128 chunk xor.
    char* zrow = SA + sub * 16384 + (row >> 3) * 1024 + (row & 7) * 128;
    const int swx = (row & 7) << 4;

    // Prologue: build Z_0 into Z buffer 0 (plain STS.128 — no TMEM staging).
    {
        __half2 bh = u2h(bond_h[tid]);
        #pragma unroll
        for (int q = 0; q < 8; q++) {
            uint4 v;
            v.x = h2u(__hmul2(nb[4*q],   bh));
            v.y = h2u(__hmul2(nb[4*q+1], bh));
            v.z = h2u(__hmul2(nb[4*q+2], bh));
            v.w = h2u(__hmul2(nb[4*q+3], bh));
            *(uint4*)(zrow + ((q * 16) ^ swx)) = v;
        }
    }
    asm volatile("fence.proxy.async.shared::cta;" ::: "memory");
    __syncthreads();   // alloc result, mbar init, bond, Z_0 visible

    uint32_t tmem;
    asm volatile("ld.shared.b32 %0, [%1];" : "=r"(tmem) : "r"(TP));
    const uint32_t Dt = tmem;                 // D: sub0 cols 0..63, sub1 cols 64..127
    const uint32_t lane_off = (uint32_t)(row >> 5) << 21;

    #pragma unroll 1
    for (int b = 0; b < NBLK; b++) {
        asm volatile("cp.async.wait_group 1;" ::: "memory");   // W_b resident
        asm volatile("fence.proxy.async.shared::cta;" ::: "memory");
        __syncthreads();   // Z_b stores + W_b visible to the async proxy reader

        // Issue MMA_b (SS form); overlaps Z_{b+1} build and W_{b+2} staging below.
        if (warp == 0) {
            asm volatile("tcgen05.fence::after_thread_sync;" ::: "memory");
            if (elect1()) {
                int wsel = b - (b / 3) * 3;   // b % 3
                uint32_t za = ZB + (uint32_t)(b & 1) * 32768;
                uint64_t ad0 = DBASE | (uint64_t)((za >> 4) & 0x3FFF);
                uint64_t ad1 = DBASE | (uint64_t)(((za + 16384) >> 4) & 0x3FFF);
                uint64_t bd  = DBASE | (uint64_t)(((WS + wsel * 8192) >> 4) & 0x3FFF);
                #pragma unroll
                for (int k = 0; k < 4; k++) {
                    uint32_t en = (b > 0 || k > 0) ? 1u : 0u;
                    tc_mma_f16_ss(Dt,      ad0 + k * 2, bd + k * 2, en);
                    tc_mma_f16_ss(Dt + 64, ad1 + k * 2, bd + k * 2, en);
                }
                asm volatile(
                    "tcgen05.commit.cta_group::1.mbarrier::arrive::one.shared::cluster.b64 [%0];"
                    :: "r"((b & 1) ? MB1 : MB0) : "memory");
            }
        }

        if (b + 1 < NBLK) {
            if (b >= 1) {
                // Wait MMA_{b-1} on its own barrier (lag <= 1, no parity aliasing).
                // Frees Z buffer (b+1)&1 and W slot (b+2)%3.
                mbar_wait((b & 1) ? MB0 : MB1, ((b - 1) >> 1) & 1);
            }
            {
                __half2 bh = u2h(bond_h[(b + 1) * TM + tid]);
                char* zr = zrow + ((b & 1) ? 0 : 32768);   // buffer (b+1)&1
                #pragma unroll
                for (int q = 0; q < 8; q++) {
                    uint4 v;
                    v.x = h2u(__hmul2(nb[4*q],   bh));
                    v.y = h2u(__hmul2(nb[4*q+1], bh));
                    v.z = h2u(__hmul2(nb[4*q+2], bh));
                    v.w = h2u(__hmul2(nb[4*q+3], bh));
                    *(uint4*)(zr + ((q * 16) ^ swx)) = v;
                }
            }
            if (b + 2 < NBLK) {
                int dst = (b + 2) - ((b + 2) / 3) * 3;
                uint32_t da = WS + dst * 8192;
                for (int i = tid; i < TCBLK_V4; i += 256)
                    cp_async16(da + i * 16, W_tc + (b + 2) * TCBLK_V4 + i);
            }
        }
        asm volatile("cp.async.commit_group;");   // exactly one group per iteration
    }

    // Wait MMA_16 on MB0: phase 8, parity 0 (in-loop MB0 waits consumed phases 0..7).
    mbar_wait(MB0, 0);
    asm volatile("tcgen05.fence::after_thread_sync;" ::: "memory");

    // Readout + segment-sum RED.
    {
        uint32_t d0[32], d1[32];
        tmem_ld32(d0, Dt + (uint32_t)sub * 64 + lane_off);
        tmem_ld32(d1, Dt + (uint32_t)sub * 64 + 32 + lane_off);
        asm volatile("tcgen05.wait::ld.sync.aligned;" ::: "memory");
        if (src >= 0) {
            float* op = out + (size_t)src * 64;
            #pragma unroll
            for (int q = 0; q < 8; q++)
                red4(op + 4 * q, __uint_as_float(d0[4*q]),   __uint_as_float(d0[4*q+1]),
                                 __uint_as_float(d0[4*q+2]), __uint_as_float(d0[4*q+3]));
            #pragma unroll
            for (int q = 0; q < 8; q++)
                red4(op + 32 + 4 * q, __uint_as_float(d1[4*q]),   __uint_as_float(d1[4*q+1]),
                                      __uint_as_float(d1[4*q+2]), __uint_as_float(d1[4*q+3]));
        }
    }
    __syncthreads();
    if (warp == 0)
        asm volatile("tcgen05.dealloc.cta_group::1.sync.aligned.b32 %0, %1;"
                     :: "r"(tmem), "r"(128u));
#else
    // ================= fallback: mma.sync fp16 (compute_103 cubin) =================
    __shared__ uint32_t Wall[3 * WBLK_U];       // 26112 B
    __shared__ uint32_t bond_h[NBLK * TM];      // 17408 B
    __shared__ int      src_s[TM];              // 1024 B

    const int lane = tid & 31;
    const int gid  = lane >> 2, tig = lane & 3;

    #pragma unroll
    for (int g = 0; g < 2; g++) {
        for (int i = tid; i < WBLK_V4; i += 256)
            cp_async16(smem_u32(Wall) + (g * WBLK_V4 + i) * 16, W_img + g * WBLK_V4 + i);
        asm volatile("cp.async.commit_group;");
    }

    {
        int e = e0 + tid;
        int src = -1;
        float4 q0 = {0,0,0,0}, q1 = q0, q2 = q0, q3 = q0;
        float one = 0.f;
        if (e < n_edges) {
            src = ((const int2*)pair)[e].x;
            one = 1.f;
            const float4* bp = (const float4*)(bondf + (size_t)e * 16);
            q0 = bp[0]; q1 = bp[1]; q2 = bp[2]; q3 = bp[3];
        }
        src_s[tid] = src;
        const float bv[16] = {q0.x,q0.y,q0.z,q0.w, q1.x,q1.y,q1.z,q1.w,
                              q2.x,q2.y,q2.z,q2.w, q3.x,q3.y,q3.z,q3.w};
        #pragma unroll
        for (int b = 0; b < 16; b++) bond_h[b * TM + tid] = h2u(__float2half2_rn(bv[b]));
        bond_h[16 * TM + tid] = h2u(__float2half2_rn(one));
    }

    const int row0 = warp * 32 + gid;
    __half2 nb[4][8];
    #pragma unroll
    for (int r = 0; r < 4; r++) {
        int e = e0 + row0 + 8 * r;
        int nbr = (e < n_edges) ? ((const int2*)pair)[e].y : 0;
        const float2* ap = (const float2*)(atom + (size_t)nbr * 64);
        #pragma unroll
        for (int q = 0; q < 8; q++) {
            float2 v = __ldg(ap + 4 * q + tig);
            nb[r][q] = __floats2half2_rn(v.x, v.y);
        }
    }

    float c[2][8][4];
    #pragma unroll
    for (int m = 0; m < 2; m++)
        #pragma unroll
        for (int nt = 0; nt < 8; nt++)
            c[m][nt][0] = c[m][nt][1] = c[m][nt][2] = c[m][nt][3] = 0.f;

    int wb = 0;   // b % 3
    for (int b = 0; b < NBLK; b++) {
        asm volatile("cp.async.wait_group 1;" ::: "memory");
        __syncthreads();

        if (b + 2 < NBLK) {
            int dst = wb + 2 - ((wb + 2 >= 3) ? 3 : 0);
            for (int i = tid; i < WBLK_V4; i += 256)
                cp_async16(smem_u32(Wall) + (dst * WBLK_V4 + i) * 16,
                           W_img + (b + 2) * WBLK_V4 + i);
        }
        asm volatile("cp.async.commit_group;");

        __half2 bh0 = u2h(bond_h[b * TM + row0]);
        __half2 bh1 = u2h(bond_h[b * TM + row0 + 8]);
        __half2 bh2 = u2h(bond_h[b * TM + row0 + 16]);
        __half2 bh3 = u2h(bond_h[b * TM + row0 + 24]);

        const uint32_t* wbase = Wall + wb * WBLK_U + lane * SLOTP;
        #pragma unroll
        for (int s = 0; s < 4; s++) {
            uint4 q0 = *(const uint4*)(wbase + s * 16);
            uint4 q1 = *(const uint4*)(wbase + s * 16 + 4);
            uint4 q2 = *(const uint4*)(wbase + s * 16 + 8);
            uint4 q3 = *(const uint4*)(wbase + s * 16 + 12);

            uint32_t a00 = h2u(__hmul2(nb[0][2*s],   bh0));
            uint32_t a01 = h2u(__hmul2(nb[1][2*s],   bh1));
            uint32_t a02 = h2u(__hmul2(nb[0][2*s+1], bh0));
            uint32_t a03 = h2u(__hmul2(nb[1][2*s+1], bh1));
            uint32_t a10 = h2u(__hmul2(nb[2][2*s],   bh2));
            uint32_t a11 = h2u(__hmul2(nb[3][2*s],   bh3));
            uint32_t a12 = h2u(__hmul2(nb[2][2*s+1], bh2));
            uint32_t a13 = h2u(__hmul2(nb[3][2*s+1], bh3));

            mma16816(c[0][0], a00, a01, a02, a03, q0.x, q0.y);
            mma16816(c[1][0], a10, a11, a12, a13, q0.x, q0.y);
            mma16816(c[0][1], a00, a01, a02, a03, q0.z, q0.w);
            mma16816(c[1][1], a10, a11, a12, a13, q0.z, q0.w);
            mma16816(c[0][2], a00, a01, a02, a03, q1.x, q1.y);
            mma16816(c[1][2], a10, a11, a12, a13, q1.x, q1.y);
            mma16816(c[0][3], a00, a01, a02, a03, q1.z, q1.w);
            mma16816(c[1][3], a10, a11, a12, a13, q1.z, q1.w);
            mma16816(c[0][4], a00, a01, a02, a03, q2.x, q2.y);
            mma16816(c[1][4], a10, a11, a12, a13, q2.x, q2.y);
            mma16816(c[0][5], a00, a01, a02, a03, q2.z, q2.w);
            mma16816(c[1][5], a10, a11, a12, a13, q2.z, q2.w);
            mma16816(c[0][6], a00, a01, a02, a03, q3.x, q3.y);
            mma16816(c[1][6], a10, a11, a12, a13, q3.x, q3.y);
            mma16816(c[0][7], a00, a01, a02, a03, q3.z, q3.w);
            mma16816(c[1][7], a10, a11, a12, a13, q3.z, q3.w);
        }
        wb = (wb == 2) ? 0 : wb + 1;
    }

    const bool even = (tig & 1) == 0;
    #pragma unroll
    for (int m = 0; m < 2; m++) {
        int srcA = src_s[warp * 32 + m * 16 + gid];
        int srcB = src_s[warp * 32 + m * 16 + gid + 8];
        int msrc = even ? srcA : srcB;
        int colbase = 4 * (tig >> 1);
        #pragma unroll
        for (int nt = 0; nt < 8; nt++) {
            float c0 = c[m][nt][0], c1 = c[m][nt][1], c2 = c[m][nt][2], c3 = c[m][nt][3];
            float g0 = __shfl_xor_sync(0xffffffffu, c0, 1);
            float g1 = __shfl_xor_sync(0xffffffffu, c1, 1);
            float g2 = __shfl_xor_sync(0xffffffffu, c2, 1);
            float g3 = __shfl_xor_sync(0xffffffffu, c3, 1);
            float q0 = even ? c0 : g2;
            float q1 = even ? c1 : g3;
            float q2 = even ? g0 : c2;
            float q3 = even ? g1 : c3;
            if (msrc >= 0)
                red4(out + (size_t)msrc * 64 + nt * 8 + colbase, q0, q1, q2, q3);
        }
    }
#endif
}

extern "C" void kernel_launch(void* const* d_in, const int* in_sizes, int n_in,
                              void* d_out, int out_size) {
    const float* atom  = (const float*)d_in[0];
    const float* bondf = (const float*)d_in[1];
    const int*   pair  = (const int*)d_in[2];
    const float* K     = (const float*)d_in[3];
    const float* bias  = (const float*)d_in[4];
    float* out = (float*)d_out;

    int n_edges = in_sizes[2] / 2;
    int n_out4  = out_size / 4;

    zero_pack<<<(n_out4 + 255) / 256, 256>>>(K, bias, (float4*)out, n_out4);

    cudaFuncSetAttribute(edge_main, cudaFuncAttributeMaxDynamicSharedMemorySize, DSM_SZ);
    int grid = (n_edges + TM - 1) / TM;
    edge_main<<<grid, 256, DSM_SZ>>>(atom, bondf, pair, out, n_edges);
}

// round 11
// speedup vs baseline: 1.2209x; 1.2209x over previous
#include <cuda_runtime.h>
#include <cuda_fp16.h>
#include <cstdint>

#define TM      256
#define NBLK    17
#define NC      6            // chunks of 3 b-blocks (last chunk has 2)
// ---- fallback (mma.sync) W layout: per-lane-contiguous, pitch 68 ----
#define SLOTP   68
#define WBLK_U  (32 * SLOTP)        // 2176 uints per block
#define WBLK_V4 (WBLK_U / 4)        // 544
// ---- tcgen05 W layout: SW128 blocked-atom f16 image, 8 KB per block ----
#define TCBLK_U  2048
#define TCBLK_V4 512

__device__ uint4 W_img[NBLK * WBLK_V4];   // fallback image
__device__ uint4 W_tc [NBLK * TCBLK_V4];  // tcgen05 image

// tcgen05 dynamic smem (from 1024-aligned base):
//   W: 3 chunk slots x 24576 B | bond: 17*256*4 | hdr: tmem ptr + 2 mbarriers
#define OFF_BOND 73728
#define OFF_HDR  91136
#define DSM_SZ   (91136 + 32 + 1024)

// ---------------- shared helpers ----------------
static __device__ __forceinline__ void cp_async16(uint32_t s, const void* g) {
    asm volatile("cp.async.cg.shared.global [%0], [%1], 16;" :: "r"(s), "l"(g));
}
static __device__ __forceinline__ uint32_t smem_u32(const void* p) {
    uint32_t a;
    asm("{ .reg .u64 t; cvta.to.shared.u64 t, %1; cvt.u32.u64 %0, t; }" : "=r"(a) : "l"(p));
    return a;
}
static __device__ __forceinline__ uint32_t h2u(__half2 h) {
    return *reinterpret_cast<uint32_t*>(&h);
}
static __device__ __forceinline__ __half2 u2h(uint32_t u) {
    return *reinterpret_cast<__half2*>(&u);
}
static __device__ __forceinline__ void red4(float* p, float a, float b, float c, float d) {
    asm volatile("red.global.add.v4.f32 [%0], {%1, %2, %3, %4};"
                 :: "l"(p), "f"(a), "f"(b), "f"(c), "f"(d) : "memory");
}
static __device__ __forceinline__ void mma16816(float* c, uint32_t a0, uint32_t a1,
                                                uint32_t a2, uint32_t a3,
                                                uint32_t b0, uint32_t b1) {
    asm volatile(
        "mma.sync.aligned.m16n8k16.row.col.f32.f16.f16.f32 "
        "{%0,%1,%2,%3}, {%4,%5,%6,%7}, {%8,%9}, {%0,%1,%2,%3};"
        : "+f"(c[0]), "+f"(c[1]), "+f"(c[2]), "+f"(c[3])
        : "r"(a0), "r"(a1), "r"(a2), "r"(a3), "r"(b0), "r"(b1));
}

// ---------------- tcgen05 helpers ----------------
#if defined(__CUDA_ARCH__) && defined(__CUDA_ARCH_FEAT_SM103_ALL)
#define TC_IDESC ((1u << 4) | (8u << 17) | (8u << 24))   // kind::f16: fp16 in, f32 acc, M=128, N=64
#define DBASE ((2ull << 61) | (1ull << 46) | (64ull << 32) | (1ull << 16))  // SW128, v1, SBO=64, LBO=1

static __device__ __forceinline__ bool elect1() {
    uint32_t p;
    asm volatile("{ .reg .pred P; elect.sync _|P, 0xFFFFFFFF; selp.b32 %0, 1, 0, P; }" : "=r"(p));
    return p != 0;
}
static __device__ __forceinline__ void mbar_init(uint32_t a, uint32_t c) {
    asm volatile("mbarrier.init.shared.b64 [%0], %1;" :: "r"(a), "r"(c) : "memory");
}
static __device__ __forceinline__ void mbar_wait(uint32_t a, uint32_t ph) {
    asm volatile(
        "{ .reg .pred P;\n"
        "LW_%=:\n"
        "mbarrier.try_wait.parity.acquire.cta.shared::cta.b64 P, [%0], %1, 0x989680;\n"
        "@!P bra LW_%=;\n"
        "}" :: "r"(a), "r"(ph) : "memory");
}
static __device__ __forceinline__ void tc_mma_f16(uint32_t d, uint32_t a, uint64_t bd,
                                                  uint32_t en) {
    asm volatile(
        "{ .reg .pred p; setp.ne.u32 p, %5, 0;\n"
        "tcgen05.mma.cta_group::1.kind::f16 [%0], [%1], %2, %3, {%4, %4, %4, %4}, p;\n"
        "}"
        :: "r"(d), "r"(a), "l"(bd), "r"(TC_IDESC), "r"(0u), "r"(en) : "memory");
}
static __device__ __forceinline__ void tmem_st32(uint32_t addr, const uint32_t* r) {
    asm volatile(
        "tcgen05.st.sync.aligned.32x32b.x32.b32 [%0], "
        "{%1,%2,%3,%4,%5,%6,%7,%8,%9,%10,%11,%12,%13,%14,%15,%16,"
        "%17,%18,%19,%20,%21,%22,%23,%24,%25,%26,%27,%28,%29,%30,%31,%32};"
        :: "r"(addr),
           "r"(r[0]),  "r"(r[1]),  "r"(r[2]),  "r"(r[3]),
           "r"(r[4]),  "r"(r[5]),  "r"(r[6]),  "r"(r[7]),
           "r"(r[8]),  "r"(r[9]),  "r"(r[10]), "r"(r[11]),
           "r"(r[12]), "r"(r[13]), "r"(r[14]), "r"(r[15]),
           "r"(r[16]), "r"(r[17]), "r"(r[18]), "r"(r[19]),
           "r"(r[20]), "r"(r[21]), "r"(r[22]), "r"(r[23]),
           "r"(r[24]), "r"(r[25]), "r"(r[26]), "r"(r[27]),
           "r"(r[28]), "r"(r[29]), "r"(r[30]), "r"(r[31])
        : "memory");
}
static __device__ __forceinline__ void tmem_ld32(uint32_t* r, uint32_t addr) {
    asm volatile(
        "tcgen05.ld.sync.aligned.32x32b.x32.b32 "
        "{%0,%1,%2,%3,%4,%5,%6,%7,%8,%9,%10,%11,%12,%13,%14,%15,"
        "%16,%17,%18,%19,%20,%21,%22,%23,%24,%25,%26,%27,%28,%29,%30,%31}, [%32];"
        : "=r"(r[0]),  "=r"(r[1]),  "=r"(r[2]),  "=r"(r[3]),
          "=r"(r[4]),  "=r"(r[5]),  "=r"(r[6]),  "=r"(r[7]),
          "=r"(r[8]),  "=r"(r[9]),  "=r"(r[10]), "=r"(r[11]),
          "=r"(r[12]), "=r"(r[13]), "=r"(r[14]), "=r"(r[15]),
          "=r"(r[16]), "=r"(r[17]), "=r"(r[18]), "=r"(r[19]),
          "=r"(r[20]), "=r"(r[21]), "=r"(r[22]), "=r"(r[23]),
          "=r"(r[24]), "=r"(r[25]), "=r"(r[26]), "=r"(r[27]),
          "=r"(r[28]), "=r"(r[29]), "=r"(r[30]), "=r"(r[31])
        : "r"(addr));
}
#endif

// ---------------- zero output + pack both W images ----------------
__global__ void __launch_bounds__(256)
zero_pack(const float* __restrict__ K, const float* __restrict__ bias,
          float4* __restrict__ out4, int n_out4) {
    int idx = blockIdx.x * blockDim.x + threadIdx.x;
    if (idx < n_out4) out4[idx] = make_float4(0.f, 0.f, 0.f, 0.f);
    if (idx < NBLK * 2048) {
        int b = idx >> 11, r = idx & 2047;
        // fallback image: per-lane-contiguous values
        {
            int slot = r >> 6, v = r & 63;
            int gid = slot >> 2, tig = slot & 3;
            int s = v >> 4, r2 = v & 15, nt = r2 >> 1, h = r2 & 1;
            int p = 8 * s + tig + 4 * h;
            int n = nt * 8 + gid;
            float v0, v1;
            if (b < 16) { v0 = K[b * 4096 + n * 64 + 2 * p]; v1 = K[b * 4096 + n * 64 + 2 * p + 1]; }
            else        { v0 = bias[n * 64 + 2 * p];          v1 = bias[n * 64 + 2 * p + 1]; }
            ((uint32_t*)W_img)[b * WBLK_U + slot * SLOTP + v] = h2u(__floats2half2_rn(v0, v1));
        }
        // tcgen05 image: B[n][k] f16, SW128 atoms (8 rows x 128 B)
        {
            int n = r >> 5, p = r & 31;
            float v0, v1;
            if (b < 16) { v0 = K[b * 4096 + n * 64 + 2 * p]; v1 = K[b * 4096 + n * 64 + 2 * p + 1]; }
            else        { v0 = bias[n * 64 + 2 * p];          v1 = bias[n * 64 + 2 * p + 1]; }
            int byte = (n >> 3) * 1024 + (n & 7) * 128 + p * 4;
            int sw = byte ^ ((byte >> 3) & 0x70);
            ((uint32_t*)W_tc)[b * TCBLK_U + (sw >> 2)] = h2u(__floats2half2_rn(v0, v1));
        }
    }
}

extern __shared__ char dsm_raw[];

__global__ void __launch_bounds__(256, 2)
edge_main(const float* __restrict__ atom, const float* __restrict__ bondf,
          const int* __restrict__ pair, float* __restrict__ out, int n_edges)
{
    const int tid  = threadIdx.x;
    const int warp = tid >> 5;
    const int e0   = blockIdx.x * TM;

#if defined(__CUDA_ARCH__) && defined(__CUDA_ARCH_FEAT_SM103_ALL)
    // ========== tcgen05 TS path, CHUNKED: 3 b-blocks per iteration (6 iters) ==========
    const uint32_t raw  = smem_u32(dsm_raw);
    const uint32_t base = (raw + 1023u) & ~1023u;
    char* SA = dsm_raw + (base - raw);

    const uint32_t WS  = base;                        // 3 slots x 24576
    uint32_t* bond_h   = (uint32_t*)(SA + OFF_BOND);  // [17][256]
    const uint32_t TP  = base + OFF_HDR;
    const uint32_t MB0 = TP + 8;
    const uint32_t MB1 = TP + 16;

    const int sub = tid >> 7;
    const int row = tid & 127;
    const int e   = e0 + tid;

    if (warp == 0) {
        asm volatile("tcgen05.alloc.cta_group::1.sync.aligned.shared::cta.b32 [%0], %1;"
                     :: "r"(TP), "r"(512u) : "memory");
        asm volatile("tcgen05.relinquish_alloc_permit.cta_group::1.sync.aligned;");
    }
    if (tid == 0) { mbar_init(MB0, 1); mbar_init(MB1, 1); }

    // Stage W chunk 0 (blocks 0-2) and chunk 1 (blocks 3-5) as groups 0, 1.
    #pragma unroll
    for (int g = 0; g < 2; g++) {
        for (int i = tid; i < 3 * TCBLK_V4; i += 256)
            cp_async16(WS + g * 24576 + i * 16, W_tc + g * 3 * TCBLK_V4 + i);
        asm volatile("cp.async.commit_group;");
    }

    // Stage bond (dup half2); src in register; neighbor row -> 32 half2 regs.
    int src = -1, nbr = 0;
    {
        float4 q0 = {0,0,0,0}, q1 = q0, q2 = q0, q3 = q0;
        float one = 0.f;
        if (e < n_edges) {
            int2 pr = ((const int2*)pair)[e];
            src = pr.x; nbr = pr.y; one = 1.f;
            const float4* bp = (const float4*)(bondf + (size_t)e * 16);
            q0 = bp[0]; q1 = bp[1]; q2 = bp[2]; q3 = bp[3];
        }
        const float bv[16] = {q0.x,q0.y,q0.z,q0.w, q1.x,q1.y,q1.z,q1.w,
                              q2.x,q2.y,q2.z,q2.w, q3.x,q3.y,q3.z,q3.w};
        #pragma unroll
        for (int b = 0; b < 16; b++) bond_h[b * TM + tid] = h2u(__float2half2_rn(bv[b]));
        bond_h[16 * TM + tid] = h2u(__float2half2_rn(one));
    }
    __half2 nb[32];
    {
        const float4* ap = (const float4*)(atom + (size_t)nbr * 64);
        #pragma unroll
        for (int q = 0; q < 16; q++) {
            float4 v = __ldg(ap + q);
            nb[2 * q]     = __floats2half2_rn(v.x, v.y);
            nb[2 * q + 1] = __floats2half2_rn(v.z, v.w);
        }
    }
    __syncthreads();   // alloc result, mbar init, bond visible

    uint32_t tmem;
    asm volatile("ld.shared.b32 %0, [%1];" : "=r"(tmem) : "r"(TP));
    const uint32_t Dt = tmem;                      // 128 cols: sub0 0..63, sub1 64..127
    const uint32_t AG0 = tmem + 128;               // A group 0: 192 cols (3 blocks x 64)
    const uint32_t AG1 = tmem + 320;               // A group 1: 192 cols
    const uint32_t lane_off = (uint32_t)(row >> 5) << 21;
    const uint32_t aoff = (uint32_t)sub * 32 + lane_off;

    // Prologue: build Z for chunk 0 (blocks 0,1,2) into group 0.
    {
        #pragma unroll
        for (int t = 0; t < 3; t++) {
            __half2 bh = u2h(bond_h[t * TM + tid]);
            uint32_t z[32];
            #pragma unroll
            for (int j = 0; j < 32; j++) z[j] = h2u(__hmul2(nb[j], bh));
            tmem_st32(AG0 + (uint32_t)t * 64 + aoff, z);
        }
        asm volatile("tcgen05.wait::st.sync.aligned;" ::: "memory");
        asm volatile("tcgen05.fence::before_thread_sync;" ::: "memory");
    }

    #pragma unroll 1
    for (int c = 0; c < NC; c++) {
        const int nblk_c = (c == NC - 1) ? 2 : 3;       // blocks in this chunk
        asm volatile("cp.async.wait_group 1;" ::: "memory");   // W chunk c resident
        asm volatile("fence.proxy.async.shared::cta;" ::: "memory");
        __syncthreads();   // Z chunk c (all warps) + W chunk c visible

        // Issue all MMAs of chunk c; overlaps next chunk's Z build + W staging.
        if (warp == 0) {
            asm volatile("tcgen05.fence::after_thread_sync;" ::: "memory");
            if (elect1()) {
                int wsel = c - (c / 3) * 3;   // c % 3
                uint32_t ag = (c & 1) ? AG1 : AG0;
                #pragma unroll
                for (int t = 0; t < 3; t++) {
                    if (t >= nblk_c) break;
                    uint64_t bd = DBASE | (uint64_t)(((WS + wsel * 24576 + t * 8192) >> 4) & 0x3FFF);
                    uint32_t aa = ag + (uint32_t)t * 64;
                    #pragma unroll
                    for (int k = 0; k < 4; k++) {
                        uint32_t en = (c > 0 || t > 0 || k > 0) ? 1u : 0u;
                        tc_mma_f16(Dt,      aa      + k * 8, bd + k * 2, en);
                        tc_mma_f16(Dt + 64, aa + 32 + k * 8, bd + k * 2, en);
                    }
                }
                asm volatile(
                    "tcgen05.commit.cta_group::1.mbarrier::arrive::one.shared::cluster.b64 [%0];"
                    :: "r"((c & 1) ? MB1 : MB0) : "memory");
            }
        }

        if (c + 1 < NC) {
            if (c >= 1) {
                // Wait chunk c-1 on its barrier: phase (c-1)/2, parity ((c-1)>>1)&1.
                // Frees A group (c+1)&1 and W slot (c+2)%3.
                mbar_wait((c & 1) ? MB0 : MB1, ((c - 1) >> 1) & 1);
                asm volatile("tcgen05.fence::after_thread_sync;" ::: "memory");
            }
            // Build Z for chunk c+1 into group (c+1)&1.
            {
                uint32_t ag = (c & 1) ? AG0 : AG1;
                int b0 = 3 * (c + 1);
                int nblk_n = (c + 1 == NC - 1) ? 2 : 3;
                #pragma unroll
                for (int t = 0; t < 3; t++) {
                    if (t >= nblk_n) break;
                    __half2 bh = u2h(bond_h[(b0 + t) * TM + tid]);
                    uint32_t z[32];
                    #pragma unroll
                    for (int j = 0; j < 32; j++) z[j] = h2u(__hmul2(nb[j], bh));
                    tmem_st32(ag + (uint32_t)t * 64 + aoff, z);
                }
                asm volatile("tcgen05.wait::st.sync.aligned;" ::: "memory");
                asm volatile("tcgen05.fence::before_thread_sync;" ::: "memory");
            }
            // Stage W chunk c+2 into slot (c+2)%3 (its previous reader, chunk c-1, was waited).
            if (c + 2 < NC) {
                int dst = (c + 2) - ((c + 2) / 3) * 3;
                int b0 = 3 * (c + 2);
                int nb_c = (c + 2 == NC - 1) ? 2 : 3;
                uint32_t da = WS + dst * 24576;
                for (int i = tid; i < nb_c * TCBLK_V4; i += 256)
                    cp_async16(da + i * 16, W_tc + b0 * TCBLK_V4 + i);
            }
        }
        asm volatile("cp.async.commit_group;");   // exactly one group per iteration
    }

    // Final: wait chunk 5 on MB1, phase 2, parity 0 (in-loop MB1 waits consumed phases 0,1).
    mbar_wait(MB1, 0);
    asm volatile("tcgen05.fence::after_thread_sync;" ::: "memory");

    // Readout + segment-sum RED.
    {
        uint32_t d0[32], d1[32];
        tmem_ld32(d0, Dt + (uint32_t)sub * 64 + lane_off);
        tmem_ld32(d1, Dt + (uint32_t)sub * 64 + 32 + lane_off);
        asm volatile("tcgen05.wait::ld.sync.aligned;" ::: "memory");
        if (src >= 0) {
            float* op = out + (size_t)src * 64;
            #pragma unroll
            for (int q = 0; q < 8; q++)
                red4(op + 4 * q, __uint_as_float(d0[4*q]),   __uint_as_float(d0[4*q+1]),
                                 __uint_as_float(d0[4*q+2]), __uint_as_float(d0[4*q+3]));
            #pragma unroll
            for (int q = 0; q < 8; q++)
                red4(op + 32 + 4 * q, __uint_as_float(d1[4*q]),   __uint_as_float(d1[4*q+1]),
                                      __uint_as_float(d1[4*q+2]), __uint_as_float(d1[4*q+3]));
        }
    }
    __syncthreads();
    if (warp == 0)
        asm volatile("tcgen05.dealloc.cta_group::1.sync.aligned.b32 %0, %1;"
                     :: "r"(tmem), "r"(512u));
#else
    // ================= fallback: mma.sync fp16 (compute_103 cubin) =================
    __shared__ uint32_t Wall[3 * WBLK_U];       // 26112 B
    __shared__ uint32_t bond_h[NBLK * TM];      // 17408 B
    __shared__ int      src_s[TM];              // 1024 B

    const int lane = tid & 31;
    const int gid  = lane >> 2, tig = lane & 3;

    #pragma unroll
    for (int g = 0; g < 2; g++) {
        for (int i = tid; i < WBLK_V4; i += 256)
            cp_async16(smem_u32(Wall) + (g * WBLK_V4 + i) * 16, W_img + g * WBLK_V4 + i);
        asm volatile("cp.async.commit_group;");
    }

    {
        int e = e0 + tid;
        int src = -1;
        float4 q0 = {0,0,0,0}, q1 = q0, q2 = q0, q3 = q0;
        float one = 0.f;
        if (e < n_edges) {
            src = ((const int2*)pair)[e].x;
            one = 1.f;
            const float4* bp = (const float4*)(bondf + (size_t)e * 16);
            q0 = bp[0]; q1 = bp[1]; q2 = bp[2]; q3 = bp[3];
        }
        src_s[tid] = src;
        const float bv[16] = {q0.x,q0.y,q0.z,q0.w, q1.x,q1.y,q1.z,q1.w,
                              q2.x,q2.y,q2.z,q2.w, q3.x,q3.y,q3.z,q3.w};
        #pragma unroll
        for (int b = 0; b < 16; b++) bond_h[b * TM + tid] = h2u(__float2half2_rn(bv[b]));
        bond_h[16 * TM + tid] = h2u(__float2half2_rn(one));
    }

    const int row0 = warp * 32 + gid;
    __half2 nb[4][8];
    #pragma unroll
    for (int r = 0; r < 4; r++) {
        int e = e0 + row0 + 8 * r;
        int nbr = (e < n_edges) ? ((const int2*)pair)[e].y : 0;
        const float2* ap = (const float2*)(atom + (size_t)nbr * 64);
        #pragma unroll
        for (int q = 0; q < 8; q++) {
            float2 v = __ldg(ap + 4 * q + tig);
            nb[r][q] = __floats2half2_rn(v.x, v.y);
        }
    }

    float c[2][8][4];
    #pragma unroll
    for (int m = 0; m < 2; m++)
        #pragma unroll
        for (int nt = 0; nt < 8; nt++)
            c[m][nt][0] = c[m][nt][1] = c[m][nt][2] = c[m][nt][3] = 0.f;

    int wb = 0;   // b % 3
    for (int b = 0; b < NBLK; b++) {
        asm volatile("cp.async.wait_group 1;" ::: "memory");
        __syncthreads();

        if (b + 2 < NBLK) {
            int dst = wb + 2 - ((wb + 2 >= 3) ? 3 : 0);
            for (int i = tid; i < WBLK_V4; i += 256)
                cp_async16(smem_u32(Wall) + (dst * WBLK_V4 + i) * 16,
                           W_img + (b + 2) * WBLK_V4 + i);
        }
        asm volatile("cp.async.commit_group;");

        __half2 bh0 = u2h(bond_h[b * TM + row0]);
        __half2 bh1 = u2h(bond_h[b * TM + row0 + 8]);
        __half2 bh2 = u2h(bond_h[b * TM + row0 + 16]);
        __half2 bh3 = u2h(bond_h[b * TM + row0 + 24]);

        const uint32_t* wbase = Wall + wb * WBLK_U + lane * SLOTP;
        #pragma unroll
        for (int s = 0; s < 4; s++) {
            uint4 q0 = *(const uint4*)(wbase + s * 16);
            uint4 q1 = *(const uint4*)(wbase + s * 16 + 4);
            uint4 q2 = *(const uint4*)(wbase + s * 16 + 8);
            uint4 q3 = *(const uint4*)(wbase + s * 16 + 12);

            uint32_t a00 = h2u(__hmul2(nb[0][2*s],   bh0));
            uint32_t a01 = h2u(__hmul2(nb[1][2*s],   bh1));
            uint32_t a02 = h2u(__hmul2(nb[0][2*s+1], bh0));
            uint32_t a03 = h2u(__hmul2(nb[1][2*s+1], bh1));
            uint32_t a10 = h2u(__hmul2(nb[2][2*s],   bh2));
            uint32_t a11 = h2u(__hmul2(nb[3][2*s],   bh3));
            uint32_t a12 = h2u(__hmul2(nb[2][2*s+1], bh2));
            uint32_t a13 = h2u(__hmul2(nb[3][2*s+1], bh3));

            mma16816(c[0][0], a00, a01, a02, a03, q0.x, q0.y);
            mma16816(c[1][0], a10, a11, a12, a13, q0.x, q0.y);
            mma16816(c[0][1], a00, a01, a02, a03, q0.z, q0.w);
            mma16816(c[1][1], a10, a11, a12, a13, q0.z, q0.w);
            mma16816(c[0][2], a00, a01, a02, a03, q1.x, q1.y);
            mma16816(c[1][2], a10, a11, a12, a13, q1.x, q1.y);
            mma16816(c[0][3], a00, a01, a02, a03, q1.z, q1.w);
            mma16816(c[1][3], a10, a11, a12, a13, q1.z, q1.w);
            mma16816(c[0][4], a00, a01, a02, a03, q2.x, q2.y);
            mma16816(c[1][4], a10, a11, a12, a13, q2.x, q2.y);
            mma16816(c[0][5], a00, a01, a02, a03, q2.z, q2.w);
            mma16816(c[1][5], a10, a11, a12, a13, q2.z, q2.w);
            mma16816(c[0][6], a00, a01, a02, a03, q3.x, q3.y);
            mma16816(c[1][6], a10, a11, a12, a13, q3.x, q3.y);
            mma16816(c[0][7], a00, a01, a02, a03, q3.z, q3.w);
            mma16816(c[1][7], a10, a11, a12, a13, q3.z, q3.w);
        }
        wb = (wb == 2) ? 0 : wb + 1;
    }

    const bool even = (tig & 1) == 0;
    #pragma unroll
    for (int m = 0; m < 2; m++) {
        int srcA = src_s[warp * 32 + m * 16 + gid];
        int srcB = src_s[warp * 32 + m * 16 + gid + 8];
        int msrc = even ? srcA : srcB;
        int colbase = 4 * (tig >> 1);
        #pragma unroll
        for (int nt = 0; nt < 8; nt++) {
            float c0 = c[m][nt][0], c1 = c[m][nt][1], c2 = c[m][nt][2], c3 = c[m][nt][3];
            float g0 = __shfl_xor_sync(0xffffffffu, c0, 1);
            float g1 = __shfl_xor_sync(0xffffffffu, c1, 1);
            float g2 = __shfl_xor_sync(0xffffffffu, c2, 1);
            float g3 = __shfl_xor_sync(0xffffffffu, c3, 1);
            float q0 = even ? c0 : g2;
            float q1 = even ? c1 : g3;
            float q2 = even ? g0 : c2;
            float q3 = even ? g1 : c3;
            if (msrc >= 0)
                red4(out + (size_t)msrc * 64 + nt * 8 + colbase, q0, q1, q2, q3);
        }
    }
#endif
}

extern "C" void kernel_launch(void* const* d_in, const int* in_sizes, int n_in,
                              void* d_out, int out_size) {
    const float* atom  = (const float*)d_in[0];
    const float* bondf = (const float*)d_in[1];
    const int*   pair  = (const int*)d_in[2];
    const float* K     = (const float*)d_in[3];
    const float* bias  = (const float*)d_in[4];
    float* out = (float*)d_out;

    int n_edges = in_sizes[2] / 2;
    int n_out4  = out_size / 4;

    zero_pack<<<(n_out4 + 255) / 256, 256>>>(K, bias, (float4*)out, n_out4);

    cudaFuncSetAttribute(edge_main, cudaFuncAttributeMaxDynamicSharedMemorySize, DSM_SZ);
    int grid = (n_edges + TM - 1) / TM;
    edge_main<<<grid, 256, DSM_SZ>>>(atom, bondf, pair, out, n_edges);
}